// round 9
// baseline (speedup 1.0000x reference)
#include <cuda_runtime.h>

#define NN 2048
#define KK 16
#define FF 256
#define OO 256
#define RT 32   // gcn1 row tile
#define NJS 4   // gcn1 j-split
#define RT2 16  // gcn2 row tile
#define FCH 4   // final chunk split

// ---- scratch (static device memory; no allocation) ----
__device__ unsigned int g_mask[NN];
__device__ int   g_list[KK * NN];
__device__ int   g_cnt[KK];
__device__ float g_h[NN * OO];
__device__ float g_colsum[OO];
__device__ float g_colsumsq[OO];
__device__ float g_U[KK * NN];
__device__ float g_V[NJS][KK * NN * FF / 2];  // V partials per j-quarter (quarter<=NN/2 rows used? sized generously below)
__device__ int   g_sync0;

// NOTE: g_V sizing: each js-partial needs KK*NN*FF floats. Use full size per slice.
__device__ float g_Vs[NJS * KK * NN * FF];

// ---------------------------------------------------------------
// K1) assignment mask + fused zeroing (incl. out); LAST block builds lists.
// ---------------------------------------------------------------
__global__ void __launch_bounds__(256) assign_kernel(const float* __restrict__ x,
                                                     const float* __restrict__ w,
                                                     const float* __restrict__ b,
                                                     float* __restrict__ out) {
    __shared__ unsigned bal_sh[64][KK];
    __shared__ int      off_sh[64][KK];
    __shared__ int      last_flag;

    int tid = threadIdx.x;
    int gt = blockIdx.x * 256 + tid;
#pragma unroll
    for (int r = 0; r < 8; r++) g_h[gt + r * 65536] = 0.f;
    if (gt < KK * NN) g_U[gt] = 0.f;
    if (gt < OO) { g_colsum[gt] = 0.f; g_colsumsq[gt] = 0.f; }
    if (gt < KK * OO + KK * KK) out[gt] = 0.f;

    int node = gt >> 5;
    int lane = tid & 31;
    int warp = tid >> 5;
    float p[KK];
#pragma unroll
    for (int k = 0; k < KK; k++) p[k] = 0.f;
    const float* xr = x + node * FF;
    for (int f = lane; f < FF; f += 32) {
        float xv = xr[f];
        const float* wr = w + f * KK;
#pragma unroll
        for (int k = 0; k < KK; k++) p[k] += xv * wr[k];
    }
#pragma unroll
    for (int k = 0; k < KK; k++) {
#pragma unroll
        for (int off = 16; off >= 1; off >>= 1)
            p[k] += __shfl_xor_sync(0xffffffffu, p[k], off);
    }
    if (lane == 0) {
        float m = 0.f;
#pragma unroll
        for (int k = 0; k < KK; k++) {
            p[k] = fmaxf(p[k] + b[k], 0.f);
            m = fmaxf(m, p[k]);
        }
        unsigned mask = 0u;
#pragma unroll
        for (int k = 0; k < KK; k++)
            if (p[k] == m) mask |= (1u << k);
        g_mask[node] = mask;
    }
    __syncthreads();

    if (tid == 0) {
        __threadfence();
        int old = atomicAdd(&g_sync0, 1);
        last_flag = (old == 255);
    }
    __syncthreads();
    if (!last_flag) return;
    if (tid == 0) g_sync0 = 0;
    __threadfence();

    for (int c = warp; c < 64; c += 8) {
        unsigned m = g_mask[c * 32 + lane];
#pragma unroll
        for (int k = 0; k < KK; k++) {
            unsigned bal = __ballot_sync(0xffffffffu, (m >> k) & 1u);
            if (lane == k) bal_sh[c][k] = bal;
        }
    }
    __syncthreads();
    if (tid < KK) {
        int s = 0;
        for (int c = 0; c < 64; c++) {
            off_sh[c][tid] = s;
            s += __popc(bal_sh[c][tid]);
        }
        g_cnt[tid] = s;
    }
    __syncthreads();
    for (int c = warp; c < 64; c += 8) {
#pragma unroll
        for (int k = 0; k < KK; k++) {
            unsigned bal = bal_sh[c][k];
            if ((bal >> lane) & 1u)
                g_list[k * NN + off_sh[c][k] + __popc(bal & ((1u << lane) - 1u))]
                    = c * 32 + lane;
        }
    }
}

// ---------------------------------------------------------------
// K2) fat kernel: blocks [0,256) coarsenU; rest gcn1 (RT=32, NJS=4).
// ---------------------------------------------------------------
__global__ void __launch_bounds__(256) mid_kernel(const float* __restrict__ x,
                                                  const float* __restrict__ adj) {
    __shared__ __align__(16) int   list_sh[NN + 64];
    __shared__ __align__(16) float a_sh[RT][68];

    int tid = threadIdx.x;
    int bb = blockIdx.x;

    if (bb < 256) {
        // ---- coarsenU role
        int bx  = bb & 7;
        int bkt = (bb >> 3) & 15;
        int bz  = bb >> 7;
        int j = bx * 256 + tid;
        int n = g_cnt[bkt];
        int half = (n + 1) >> 1;
        int s0 = bz * half;
        int s1 = s0 + half; if (s1 > n) s1 = n;
        int cnt = s1 - s0;
        for (int i = tid; i < cnt; i += 256) list_sh[i] = g_list[bkt * NN + s0 + i];
        __syncthreads();

        float a0 = 0.f, a1 = 0.f, a2 = 0.f, a3 = 0.f;
        float a4 = 0.f, a5 = 0.f, a6 = 0.f, a7 = 0.f;
        int t = 0;
        for (; t + 8 <= cnt; t += 8) {
            a0 += adj[(size_t)list_sh[t + 0] * NN + j];
            a1 += adj[(size_t)list_sh[t + 1] * NN + j];
            a2 += adj[(size_t)list_sh[t + 2] * NN + j];
            a3 += adj[(size_t)list_sh[t + 3] * NN + j];
            a4 += adj[(size_t)list_sh[t + 4] * NN + j];
            a5 += adj[(size_t)list_sh[t + 5] * NN + j];
            a6 += adj[(size_t)list_sh[t + 6] * NN + j];
            a7 += adj[(size_t)list_sh[t + 7] * NN + j];
        }
        for (; t < cnt; t++) a0 += adj[(size_t)list_sh[t] * NN + j];
        float s = ((a0 + a1) + (a2 + a3)) + ((a4 + a5) + (a6 + a7));
        if (s != 0.f) atomicAdd(&g_U[bkt * NN + j], s);
        return;
    }

    // ---- gcn1 role: RT=32 rows, j-quarter js
    int g = bb - 256;
    int gx = g & 63;            // 64 row tiles
    int k  = (g >> 6) & 15;
    int js = g >> 10;           // 0..3

    int n = g_cnt[k];
    int t0 = gx * RT;
    if (t0 >= n) return;
    int qlen = (n + NJS - 1) / NJS;
    int j0s = js * qlen;
    int j1s = j0s + qlen; if (j1s > n) j1s = n;
    if (j0s >= n && js != 0) {
        // still must write the 2x term? only js==0 carries it; nothing to do
        // but V slice must exist: write zeros
    }

    for (int i = tid; i < n; i += 256) list_sh[i] = g_list[k * NN + i];
    for (int i = n + tid; i < n + 64; i += 256) list_sh[i] = 0;
    __syncthreads();

    int rows = n - t0; if (rows > RT) rows = RT;
    int irow[RT];
#pragma unroll
    for (int r = 0; r < RT; r++) irow[r] = list_sh[t0 + (r < rows ? r : 0)];

    const int f = tid;
    float acc[RT];
    if (js == 0) {
#pragma unroll
        for (int r = 0; r < RT; r++) acc[r] = 2.f * x[(size_t)irow[r] * FF + f];
    } else {
#pragma unroll
        for (int r = 0; r < RT; r++) acc[r] = 0.f;
    }

    // pipelined gather: 8 elements/thread of the 32x64 tile
    int gr[8], gc[8];
    long arow[8];
#pragma unroll
    for (int u = 0; u < 8; u++) {
        int e = tid + 256 * u;
        gr[u] = e >> 6; gc[u] = e & 63;
        arow[u] = (size_t)irow[gr[u]] * NN;
    }

    float pre[8];
    if (j0s < j1s) {
#pragma unroll
        for (int u = 0; u < 8; u++)
            pre[u] = (j0s + gc[u] < j1s) ? adj[arow[u] + list_sh[j0s + gc[u]]] : 0.f;
    }
    for (int jc = j0s; jc < j1s; jc += 64) {
#pragma unroll
        for (int u = 0; u < 8; u++) a_sh[gr[u]][gc[u]] = pre[u];
        __syncthreads();
        int jn = jc + 64;
        if (jn < j1s) {
#pragma unroll
            for (int u = 0; u < 8; u++)
                pre[u] = (jn + gc[u] < j1s) ? adj[arow[u] + list_sh[jn + gc[u]]] : 0.f;
        }
#pragma unroll 2
        for (int c = 0; c < 64; c += 4) {
            float xv0 = x[(size_t)list_sh[jc + c + 0] * FF + f];
            float xv1 = x[(size_t)list_sh[jc + c + 1] * FF + f];
            float xv2 = x[(size_t)list_sh[jc + c + 2] * FF + f];
            float xv3 = x[(size_t)list_sh[jc + c + 3] * FF + f];
#pragma unroll
            for (int r = 0; r < RT; r++) {
                float4 a4 = *(const float4*)&a_sh[r][c];
                acc[r] += a4.x * xv0;
                acc[r] += a4.y * xv1;
                acc[r] += a4.z * xv2;
                acc[r] += a4.w * xv3;
            }
        }
        __syncthreads();
    }

    float* vout = g_Vs + ((size_t)js * KK * NN + (size_t)k * NN + t0) * FF + f;
#pragma unroll
    for (int r = 0; r < RT; r++)
        if (r < rows) vout[(size_t)r * FF] = acc[r];
}

// ---------------------------------------------------------------
// K3) gcn2 (RT2=16): v_sh = sum of 4 V partials; Z = v_sh @ W_k;
//     L2-normalize rows; atomic add into h.
// ---------------------------------------------------------------
__global__ void __launch_bounds__(256) gcn2_kernel(const float* __restrict__ gw) {
    int k = blockIdx.y;
    int n = g_cnt[k];
    int t0 = blockIdx.x * RT2;
    if (t0 >= n) return;

    __shared__ __align__(16) float v_sh[RT2][260];
    __shared__ float red_sh[RT2][8];
    __shared__ float inv_sh[RT2];

    int tid = threadIdx.x;
    int rows = n - t0; if (rows > RT2) rows = RT2;
    int irow[RT2];
#pragma unroll
    for (int r = 0; r < RT2; r++) irow[r] = g_list[k * NN + t0 + (r < rows ? r : 0)];

    const int f = tid;
    size_t base = ((size_t)k * NN + t0) * FF;
#pragma unroll
    for (int r = 0; r < RT2; r++) {
        int rr = (r < rows ? r : 0);
        size_t off = base + (size_t)rr * FF + f;
        float v = g_Vs[off]
                + g_Vs[(size_t)1 * KK * NN * FF + off]
                + g_Vs[(size_t)2 * KK * NN * FF + off]
                + g_Vs[(size_t)3 * KK * NN * FF + off];
        v_sh[r][f] = v;
    }
    __syncthreads();

    float z[RT2];
#pragma unroll
    for (int r = 0; r < RT2; r++) z[r] = 0.f;
    const float* Wk = gw + (size_t)k * FF * OO + f;
#pragma unroll 2
    for (int ff = 0; ff < FF; ff += 4) {
        float w0 = Wk[(size_t)(ff + 0) * OO];
        float w1 = Wk[(size_t)(ff + 1) * OO];
        float w2 = Wk[(size_t)(ff + 2) * OO];
        float w3 = Wk[(size_t)(ff + 3) * OO];
#pragma unroll
        for (int r = 0; r < RT2; r++) {
            float4 v4 = *(const float4*)&v_sh[r][ff];
            z[r] += v4.x * w0;
            z[r] += v4.y * w1;
            z[r] += v4.z * w2;
            z[r] += v4.w * w3;
        }
    }

    int lane = tid & 31, wrp = tid >> 5;
#pragma unroll
    for (int r = 0; r < RT2; r++) {
        float v = z[r] * z[r];
#pragma unroll
        for (int off = 16; off >= 1; off >>= 1)
            v += __shfl_xor_sync(0xffffffffu, v, off);
        if (lane == 0) red_sh[r][wrp] = v;
    }
    __syncthreads();
    if (tid < RT2) {
        float s = 0.f;
#pragma unroll
        for (int ww = 0; ww < 8; ww++) s += red_sh[tid][ww];
        inv_sh[tid] = rsqrtf(fmaxf(s, 1e-24f));
    }
    __syncthreads();

#pragma unroll
    for (int r = 0; r < RT2; r++)
        if (r < rows)
            atomicAdd(&g_h[(size_t)irow[r] * OO + f], z[r] * inv_sh[r]);
}

// ---------------------------------------------------------------
// K4) BN column statistics — 64 blocks x 32 rows (4x fewer atomics).
// ---------------------------------------------------------------
__global__ void __launch_bounds__(256) bn_stats_kernel() {
    int o = threadIdx.x;
    int r0 = blockIdx.x * 32;
    float s = 0.f, s2 = 0.f;
#pragma unroll 8
    for (int r = 0; r < 32; r++) {
        float v = fmaxf(g_h[(size_t)(r0 + r) * OO + o], 0.f);
        s += v; s2 += v * v;
    }
    atomicAdd(&g_colsum[o], s);
    atomicAdd(&g_colsumsq[o], s2);
}

// ---------------------------------------------------------------
// K5) final (chunked): partial BN-pool + partial coarsen via atomics.
// ---------------------------------------------------------------
__global__ void __launch_bounds__(256) final_kernel(float* __restrict__ out) {
    int a = blockIdx.y;
    int c = blockIdx.x;
    int o = threadIdx.x;
    __shared__ int list_sh[(NN + FCH - 1) / FCH + 4];

    int n = g_cnt[a];
    int chunk = (n + FCH - 1) / FCH;
    int s0 = c * chunk;
    int s1 = s0 + chunk; if (s1 > n) s1 = n;
    int cnt = s1 - s0; if (cnt < 0) cnt = 0;
    for (int i = o; i < cnt; i += 256) list_sh[i] = g_list[a * NN + s0 + i];
    __syncthreads();

    const float invN = 1.f / (float)NN;
    float mean = g_colsum[o] * invN;
    float var  = g_colsumsq[o] * invN - mean * mean;
    float inv  = rsqrtf(var + 1e-5f);

    float accv = 0.f;
    int t = 0;
    for (; t + 4 <= cnt; t += 4) {
        accv += fmaxf(g_h[(size_t)list_sh[t + 0] * OO + o], 0.f);
        accv += fmaxf(g_h[(size_t)list_sh[t + 1] * OO + o], 0.f);
        accv += fmaxf(g_h[(size_t)list_sh[t + 2] * OO + o], 0.f);
        accv += fmaxf(g_h[(size_t)list_sh[t + 3] * OO + o], 0.f);
    }
    for (; t < cnt; t++)
        accv += fmaxf(g_h[(size_t)list_sh[t] * OO + o], 0.f);
    float contrib = accv * inv;
    if (c == 0) contrib -= (float)n * mean * inv;
    if (contrib != 0.f) atomicAdd(&out[a * OO + o], contrib);

    int b = o >> 4, p = o & 15;
    float cpart = 0.f;
    for (int tt = p; tt < cnt; tt += 16)
        cpart += g_U[b * NN + list_sh[tt]];
#pragma unroll
    for (int off = 8; off >= 1; off >>= 1)
        cpart += __shfl_down_sync(0xffffffffu, cpart, off, 16);
    if (p == 0 && cpart != 0.f)
        atomicAdd(&out[KK * OO + b * KK + a], cpart);
}

// ---------------------------------------------------------------
extern "C" void kernel_launch(void* const* d_in, const int* in_sizes, int n_in,
                              void* d_out, int out_size) {
    const float* x      = (const float*)d_in[0];
    const float* adj    = (const float*)d_in[1];
    const float* w_part = (const float*)d_in[2];
    const float* b_part = (const float*)d_in[3];
    const float* gw     = (const float*)d_in[4];
    float* out = (float*)d_out;

    assign_kernel<<<NN / 8, 256>>>(x, w_part, b_part, out);
    mid_kernel<<<256 + (NN / RT) * KK * NJS, 256>>>(x, adj);
    gcn2_kernel<<<dim3(NN / RT2, KK), 256>>>(gw);
    bn_stats_kernel<<<NN / 32, 256>>>();
    final_kernel<<<dim3(FCH, KK), 256>>>(out);
}

// round 10
// speedup vs baseline: 1.1853x; 1.1853x over previous
#include <cuda_runtime.h>

#define NN 2048
#define KK 16
#define FF 256
#define OO 256
#define RT 8    // gcn row tile
#define FCH 4   // final chunk split

// ---- scratch (static device memory; no allocation) ----
__device__ unsigned int g_mask[NN];
__device__ int   g_list[KK * NN];
__device__ int   g_cnt[KK];
__device__ float g_h[NN * OO];
__device__ float g_colsum[OO];
__device__ float g_colsumsq[OO];
__device__ float g_U[KK * NN];   // U[b][j] = sum_{i in b} adj[i][j]

// ---------------------------------------------------------------
// 1) per-node hard assignment mask + fused zeroing of scratch & out
// ---------------------------------------------------------------
__global__ void __launch_bounds__(256) assign_kernel(const float* __restrict__ x,
                                                     const float* __restrict__ w,
                                                     const float* __restrict__ b,
                                                     float* __restrict__ out) {
    int gt = blockIdx.x * 256 + threadIdx.x;
#pragma unroll
    for (int r = 0; r < 8; r++) g_h[gt + r * 65536] = 0.f;
    if (gt < OO) { g_colsum[gt] = 0.f; g_colsumsq[gt] = 0.f; }
    if (gt < KK * OO + KK * KK) out[gt] = 0.f;

    int node = gt >> 5;
    int lane = threadIdx.x & 31;
    float p[KK];
#pragma unroll
    for (int k = 0; k < KK; k++) p[k] = 0.f;
    const float* xr = x + node * FF;
    for (int f = lane; f < FF; f += 32) {
        float xv = xr[f];
        const float* wr = w + f * KK;
#pragma unroll
        for (int k = 0; k < KK; k++) p[k] += xv * wr[k];
    }
#pragma unroll
    for (int k = 0; k < KK; k++) {
#pragma unroll
        for (int off = 16; off >= 1; off >>= 1)
            p[k] += __shfl_xor_sync(0xffffffffu, p[k], off);
    }
    if (lane == 0) {
        float m = 0.f;
#pragma unroll
        for (int k = 0; k < KK; k++) {
            p[k] = fmaxf(p[k] + b[k], 0.f);
            m = fmaxf(m, p[k]);
        }
        unsigned mask = 0u;
#pragma unroll
        for (int k = 0; k < KK; k++)
            if (p[k] == m) mask |= (1u << k);
        g_mask[node] = mask;
    }
}

// ---------------------------------------------------------------
// 2) deterministic parallel list build (single 1024-thread block)
// ---------------------------------------------------------------
__global__ void __launch_bounds__(1024) build_lists_kernel() {
    __shared__ unsigned bal_sh[64][KK];
    __shared__ int      off_sh[64][KK];
    int tid = threadIdx.x, warp = tid >> 5, lane = tid & 31;

    for (int c = warp; c < 64; c += 32) {
        unsigned m = g_mask[c * 32 + lane];
#pragma unroll
        for (int k = 0; k < KK; k++) {
            unsigned bal = __ballot_sync(0xffffffffu, (m >> k) & 1u);
            if (lane == k) bal_sh[c][k] = bal;
        }
    }
    __syncthreads();
    if (tid < KK) {
        int s = 0;
        for (int c = 0; c < 64; c++) {
            off_sh[c][tid] = s;
            s += __popc(bal_sh[c][tid]);
        }
        g_cnt[tid] = s;
    }
    __syncthreads();
    for (int c = warp; c < 64; c += 32) {
#pragma unroll
        for (int k = 0; k < KK; k++) {
            unsigned bal = bal_sh[c][k];
            if ((bal >> lane) & 1u)
                g_list[k * NN + off_sh[c][k] + __popc(bal & ((1u << lane) - 1u))]
                    = c * 32 + lane;
        }
    }
}

// ---------------------------------------------------------------
// 3) U[b][j] = sum_{i in list_b} adj[i][j]  — direct write, no atomics
// ---------------------------------------------------------------
__global__ void __launch_bounds__(256) coarsenU_kernel(const float* __restrict__ adj) {
    int bkt = blockIdx.y;
    int j = blockIdx.x * 256 + threadIdx.x;
    __shared__ int list_sh[NN];
    int n = g_cnt[bkt];
    for (int i = threadIdx.x; i < n; i += 256) list_sh[i] = g_list[bkt * NN + i];
    __syncthreads();

    float a0 = 0.f, a1 = 0.f, a2 = 0.f, a3 = 0.f;
    float a4 = 0.f, a5 = 0.f, a6 = 0.f, a7 = 0.f;
    int t = 0;
    for (; t + 8 <= n; t += 8) {
        a0 += adj[(size_t)list_sh[t + 0] * NN + j];
        a1 += adj[(size_t)list_sh[t + 1] * NN + j];
        a2 += adj[(size_t)list_sh[t + 2] * NN + j];
        a3 += adj[(size_t)list_sh[t + 3] * NN + j];
        a4 += adj[(size_t)list_sh[t + 4] * NN + j];
        a5 += adj[(size_t)list_sh[t + 5] * NN + j];
        a6 += adj[(size_t)list_sh[t + 6] * NN + j];
        a7 += adj[(size_t)list_sh[t + 7] * NN + j];
    }
    for (; t < n; t++) a0 += adj[(size_t)list_sh[t] * NN + j];
    g_U[bkt * NN + j] = ((a0 + a1) + (a2 + a3)) + ((a4 + a5) + (a6 + a7));
}

// ---------------------------------------------------------------
// 4) GCN per-group (fused, RT=8): V = A_sub @ X_sub + 2X ; Z = V @ W_k ;
//    L2-normalize rows; atomic add into h.   (the 90.1us champion version)
// ---------------------------------------------------------------
__global__ void __launch_bounds__(256) gcn_kernel(const float* __restrict__ x,
                                                  const float* __restrict__ adj,
                                                  const float* __restrict__ gw) {
    int k = blockIdx.y;
    int n = g_cnt[k];
    int t0 = blockIdx.x * RT;
    if (t0 >= n) return;

    __shared__ __align__(16) int   list_sh[NN + 64];
    __shared__ __align__(16) float a_sh[RT][68];
    __shared__ __align__(16) float v_sh[RT][260];
    __shared__ float red_sh[RT][8];
    __shared__ float inv_sh[RT];

    int tid = threadIdx.x;
    int nn = (n + 63) & ~63;
    for (int i = tid; i < nn; i += 256) list_sh[i] = (i < n) ? g_list[k * NN + i] : 0;
    __syncthreads();

    int rows = n - t0; if (rows > RT) rows = RT;
    int irow[RT];
#pragma unroll
    for (int r = 0; r < RT; r++) irow[r] = list_sh[t0 + (r < rows ? r : 0)];

    const int f = tid;
    float acc[RT];
#pragma unroll
    for (int r = 0; r < RT; r++) acc[r] = 2.f * x[(size_t)irow[r] * FF + f];

    for (int j0 = 0; j0 < n; j0 += 64) {
        int cmax = n - j0; if (cmax > 64) cmax = 64;
        for (int e = tid; e < RT * 64; e += 256) {
            int r = e >> 6, c = e & 63;
            float a = 0.f;
            if (c < cmax) {
                int rr = (r < rows) ? r : 0;
                a = adj[(size_t)list_sh[t0 + rr] * NN + list_sh[j0 + c]];
            }
            a_sh[r][c] = a;
        }
        __syncthreads();
#pragma unroll 4
        for (int c = 0; c < 64; c += 4) {
            float xv0 = x[(size_t)list_sh[j0 + c + 0] * FF + f];
            float xv1 = x[(size_t)list_sh[j0 + c + 1] * FF + f];
            float xv2 = x[(size_t)list_sh[j0 + c + 2] * FF + f];
            float xv3 = x[(size_t)list_sh[j0 + c + 3] * FF + f];
#pragma unroll
            for (int r = 0; r < RT; r++) {
                float4 a4 = *(const float4*)&a_sh[r][c];
                acc[r] += a4.x * xv0;
                acc[r] += a4.y * xv1;
                acc[r] += a4.z * xv2;
                acc[r] += a4.w * xv3;
            }
        }
        __syncthreads();
    }

#pragma unroll
    for (int r = 0; r < RT; r++) v_sh[r][f] = acc[r];
    __syncthreads();

    float z[RT];
#pragma unroll
    for (int r = 0; r < RT; r++) z[r] = 0.f;
    const float* Wk = gw + (size_t)k * FF * OO + f;
#pragma unroll 4
    for (int ff = 0; ff < FF; ff += 4) {
        float w0 = Wk[(size_t)(ff + 0) * OO];
        float w1 = Wk[(size_t)(ff + 1) * OO];
        float w2 = Wk[(size_t)(ff + 2) * OO];
        float w3 = Wk[(size_t)(ff + 3) * OO];
#pragma unroll
        for (int r = 0; r < RT; r++) {
            float4 v4 = *(const float4*)&v_sh[r][ff];
            z[r] += v4.x * w0;
            z[r] += v4.y * w1;
            z[r] += v4.z * w2;
            z[r] += v4.w * w3;
        }
    }

    int lane = tid & 31, wrp = tid >> 5;
#pragma unroll
    for (int r = 0; r < RT; r++) {
        float v = z[r] * z[r];
#pragma unroll
        for (int off = 16; off >= 1; off >>= 1)
            v += __shfl_xor_sync(0xffffffffu, v, off);
        if (lane == 0) red_sh[r][wrp] = v;
    }
    __syncthreads();
    if (tid < RT) {
        float s = 0.f;
#pragma unroll
        for (int ww = 0; ww < 8; ww++) s += red_sh[tid][ww];
        inv_sh[tid] = rsqrtf(fmaxf(s, 1e-24f));
    }
    __syncthreads();

#pragma unroll
    for (int r = 0; r < RT; r++)
        if (r < rows)
            atomicAdd(&g_h[(size_t)irow[r] * OO + f], z[r] * inv_sh[r]);
}

// ---------------------------------------------------------------
// 5) BN column statistics — 128 blocks x 16 rows, float4 loads.
// ---------------------------------------------------------------
__global__ void __launch_bounds__(64) bn_stats_kernel() {
    int t = threadIdx.x;            // 0..63 -> 4 columns each
    int c4 = t * 4;
    int r0 = blockIdx.x * 16;
    float sx = 0.f, sy = 0.f, sz = 0.f, sw = 0.f;
    float qx = 0.f, qy = 0.f, qz = 0.f, qw = 0.f;
#pragma unroll
    for (int r = 0; r < 16; r++) {
        float4 v = *(const float4*)&g_h[(size_t)(r0 + r) * OO + c4];
        v.x = fmaxf(v.x, 0.f); v.y = fmaxf(v.y, 0.f);
        v.z = fmaxf(v.z, 0.f); v.w = fmaxf(v.w, 0.f);
        sx += v.x; sy += v.y; sz += v.z; sw += v.w;
        qx += v.x * v.x; qy += v.y * v.y; qz += v.z * v.z; qw += v.w * v.w;
    }
    atomicAdd(&g_colsum[c4 + 0], sx);
    atomicAdd(&g_colsum[c4 + 1], sy);
    atomicAdd(&g_colsum[c4 + 2], sz);
    atomicAdd(&g_colsum[c4 + 3], sw);
    atomicAdd(&g_colsumsq[c4 + 0], qx);
    atomicAdd(&g_colsumsq[c4 + 1], qy);
    atomicAdd(&g_colsumsq[c4 + 2], qz);
    atomicAdd(&g_colsumsq[c4 + 3], qw);
}

// ---------------------------------------------------------------
// 6) final (chunked x4): partial BN-pool + partial coarsen via atomics
//    into pre-zeroed out.
// ---------------------------------------------------------------
__global__ void __launch_bounds__(256) final_kernel(float* __restrict__ out) {
    int a = blockIdx.y;
    int c = blockIdx.x;
    int o = threadIdx.x;
    __shared__ int list_sh[(NN + FCH - 1) / FCH + 4];

    int n = g_cnt[a];
    int chunk = (n + FCH - 1) / FCH;
    int s0 = c * chunk;
    int s1 = s0 + chunk; if (s1 > n) s1 = n;
    int cnt = s1 - s0; if (cnt < 0) cnt = 0;
    for (int i = o; i < cnt; i += 256) list_sh[i] = g_list[a * NN + s0 + i];
    __syncthreads();

    const float invN = 1.f / (float)NN;
    float mean = g_colsum[o] * invN;
    float var  = g_colsumsq[o] * invN - mean * mean;
    float inv  = rsqrtf(var + 1e-5f);

    float accv = 0.f;
    int t = 0;
    for (; t + 4 <= cnt; t += 4) {
        accv += fmaxf(g_h[(size_t)list_sh[t + 0] * OO + o], 0.f);
        accv += fmaxf(g_h[(size_t)list_sh[t + 1] * OO + o], 0.f);
        accv += fmaxf(g_h[(size_t)list_sh[t + 2] * OO + o], 0.f);
        accv += fmaxf(g_h[(size_t)list_sh[t + 3] * OO + o], 0.f);
    }
    for (; t < cnt; t++)
        accv += fmaxf(g_h[(size_t)list_sh[t] * OO + o], 0.f);
    float contrib = accv * inv;
    if (c == 0) contrib -= (float)n * mean * inv;
    if (contrib != 0.f) atomicAdd(&out[a * OO + o], contrib);

    // partial coarsen[b][a] += sum_{t in chunk} U[b][list[t]]
    int b = o >> 4, p = o & 15;
    float cpart = 0.f;
    for (int tt = p; tt < cnt; tt += 16)
        cpart += g_U[b * NN + list_sh[tt]];
#pragma unroll
    for (int off = 8; off >= 1; off >>= 1)
        cpart += __shfl_down_sync(0xffffffffu, cpart, off, 16);
    if (p == 0 && cpart != 0.f)
        atomicAdd(&out[KK * OO + b * KK + a], cpart);
}

// ---------------------------------------------------------------
extern "C" void kernel_launch(void* const* d_in, const int* in_sizes, int n_in,
                              void* d_out, int out_size) {
    const float* x      = (const float*)d_in[0];
    const float* adj    = (const float*)d_in[1];
    const float* w_part = (const float*)d_in[2];
    const float* b_part = (const float*)d_in[3];
    const float* gw     = (const float*)d_in[4];
    float* out = (float*)d_out;

    assign_kernel<<<NN / 8, 256>>>(x, w_part, b_part, out);
    build_lists_kernel<<<1, 1024>>>();
    coarsenU_kernel<<<dim3(8, KK), 256>>>(adj);
    gcn_kernel<<<dim3(NN / RT, KK), 256>>>(x, adj, gw);
    bn_stats_kernel<<<NN / 16, 64>>>();
    final_kernel<<<dim3(FCH, KK), 256>>>(out);
}